// round 3
// baseline (speedup 1.0000x reference)
#include <cuda_runtime.h>

#define IN_C    128
#define OUT_C   64
#define EDGE_DIM 16
#define EDGE_HID 32
#define NMAX    100000
#define EMAX    1600000
#define GR      64
#define KC      64

// ---------------- scratch (static device globals; no allocations) ----------
static __device__ float g_ew[EMAX];                       // edge gates
static __device__ float g_deg[NMAX];                      // weighted degree (init 1.0 = self loop)
static __device__ float g_dinv[NMAX];                     // rsqrt(deg)
static __device__ float g_xt[(long long)NMAX * OUT_C];    // x @ lin_w.T
static __device__ float g_sum[OUT_C];
static __device__ float g_sumsq[OUT_C];

// ---------------- K0: init deg=1 (self-loop weight), zero stats ------------
__global__ void k_init(int n) {
    int i = blockIdx.x * blockDim.x + threadIdx.x;
    if (i < n) g_deg[i] = 1.0f;
    if (i < OUT_C) { g_sum[i] = 0.0f; g_sumsq[i] = 0.0f; }
}

// ---------------- K1: edge MLP gate + degree accumulation ------------------
__global__ void k_edge_mlp(const float* __restrict__ ea,
                           const float* __restrict__ w1, const float* __restrict__ b1,
                           const float* __restrict__ w2, const float* __restrict__ b2,
                           const int* __restrict__ ei, int e_, int n) {
    __shared__ float sw1[EDGE_HID * EDGE_DIM];
    __shared__ float sb1[EDGE_HID];
    __shared__ float sw2[EDGE_HID];
    __shared__ float sb2;
    for (int i = threadIdx.x; i < EDGE_HID * EDGE_DIM; i += blockDim.x) sw1[i] = w1[i];
    if (threadIdx.x < EDGE_HID) { sb1[threadIdx.x] = b1[threadIdx.x]; sw2[threadIdx.x] = w2[threadIdx.x]; }
    if (threadIdx.x == 0) sb2 = b2[0];
    __syncthreads();

    int e = blockIdx.x * blockDim.x + threadIdx.x;
    if (e >= e_) return;

    float a[EDGE_DIM];
    const float4* p = (const float4*)(ea + (long long)e * EDGE_DIM);
#pragma unroll
    for (int q = 0; q < 4; q++) {
        float4 v = p[q];
        a[q * 4 + 0] = v.x; a[q * 4 + 1] = v.y; a[q * 4 + 2] = v.z; a[q * 4 + 3] = v.w;
    }

    float acc = sb2;
#pragma unroll 4
    for (int h = 0; h < EDGE_HID; ++h) {
        float s = sb1[h];
#pragma unroll
        for (int i = 0; i < EDGE_DIM; ++i) s = fmaf(a[i], sw1[h * EDGE_DIM + i], s);
        acc = fmaf(fmaxf(s, 0.0f), sw2[h], acc);
    }
    float g = 1.0f / (1.0f + __expf(-acc));
    g_ew[e] = g;
    int c = ei[e_ + e];   // target node (int32)
    if (c >= 0 && c < n) atomicAdd(&g_deg[c], g);
}

// ---------------- K2: dinv = rsqrt(deg) -------------------------------------
__global__ void k_dinv(int n) {
    int i = blockIdx.x * blockDim.x + threadIdx.x;
    if (i < n) g_dinv[i] = rsqrtf(g_deg[i]);
}

// ---------------- K3: xt = x @ lin_w.T ; out = dinv^2 * xt (self loop) ------
__global__ void k_xt(const float* __restrict__ x, const float* __restrict__ lw,
                     float* __restrict__ outacc, int n) {
    __shared__ float xs[KC][GR + 1];                 // xs[k][row]
    __shared__ __align__(16) float ws[KC][OUT_C];    // ws[k][o]
    int r0 = blockIdx.x * GR;
    int tx = threadIdx.x & 15;
    int ty = threadIdx.x >> 4;
    float acc[4][4] = {};

    for (int k0 = 0; k0 < IN_C; k0 += KC) {
        for (int i = threadIdx.x; i < GR * (KC / 4); i += 256) {
            int r = i >> 4, kq = i & 15;
            float4 v = make_float4(0.f, 0.f, 0.f, 0.f);
            if (r0 + r < n) v = *(const float4*)(x + (long long)(r0 + r) * IN_C + k0 + kq * 4);
            xs[kq * 4 + 0][r] = v.x; xs[kq * 4 + 1][r] = v.y;
            xs[kq * 4 + 2][r] = v.z; xs[kq * 4 + 3][r] = v.w;
        }
        for (int i = threadIdx.x; i < OUT_C * (KC / 4); i += 256) {
            int o = i >> 4, kq = i & 15;
            float4 v = *(const float4*)(lw + (long long)o * IN_C + k0 + kq * 4);
            ws[kq * 4 + 0][o] = v.x; ws[kq * 4 + 1][o] = v.y;
            ws[kq * 4 + 2][o] = v.z; ws[kq * 4 + 3][o] = v.w;
        }
        __syncthreads();
#pragma unroll 8
        for (int k = 0; k < KC; ++k) {
            float4 bv = *(const float4*)&ws[k][tx * 4];
            float a0 = xs[k][ty * 4 + 0];
            float a1 = xs[k][ty * 4 + 1];
            float a2 = xs[k][ty * 4 + 2];
            float a3 = xs[k][ty * 4 + 3];
            acc[0][0] = fmaf(a0, bv.x, acc[0][0]); acc[0][1] = fmaf(a0, bv.y, acc[0][1]);
            acc[0][2] = fmaf(a0, bv.z, acc[0][2]); acc[0][3] = fmaf(a0, bv.w, acc[0][3]);
            acc[1][0] = fmaf(a1, bv.x, acc[1][0]); acc[1][1] = fmaf(a1, bv.y, acc[1][1]);
            acc[1][2] = fmaf(a1, bv.z, acc[1][2]); acc[1][3] = fmaf(a1, bv.w, acc[1][3]);
            acc[2][0] = fmaf(a2, bv.x, acc[2][0]); acc[2][1] = fmaf(a2, bv.y, acc[2][1]);
            acc[2][2] = fmaf(a2, bv.z, acc[2][2]); acc[2][3] = fmaf(a2, bv.w, acc[2][3]);
            acc[3][0] = fmaf(a3, bv.x, acc[3][0]); acc[3][1] = fmaf(a3, bv.y, acc[3][1]);
            acc[3][2] = fmaf(a3, bv.z, acc[3][2]); acc[3][3] = fmaf(a3, bv.w, acc[3][3]);
        }
        __syncthreads();
    }
#pragma unroll
    for (int i = 0; i < 4; ++i) {
        int r = r0 + ty * 4 + i;
        if (r < n) {
            float d = g_dinv[r];
            float d2 = d * d;
            float4 o = make_float4(acc[i][0], acc[i][1], acc[i][2], acc[i][3]);
            *(float4*)&g_xt[(long long)r * OUT_C + tx * 4] = o;
            float4 s = make_float4(o.x * d2, o.y * d2, o.z * d2, o.w * d2);
            *(float4*)(outacc + (long long)r * OUT_C + tx * 4) = s;
        }
    }
}

// ---------------- K4: scatter messages (16 threads/edge, scalar atomics) ----
__global__ void k_scatter(const int* __restrict__ ei, float* __restrict__ outacc, int e_, int n) {
    long long gid = (long long)blockIdx.x * blockDim.x + threadIdx.x;
    int e = (int)(gid >> 4);
    if (e >= e_) return;
    int cg = ((int)gid & 15) * 4;
    int r = ei[e];
    int c = ei[e_ + e];
    if ((unsigned)r >= (unsigned)n || (unsigned)c >= (unsigned)n) return;
    float nrm = g_dinv[r] * g_ew[e] * g_dinv[c];
    float4 v = *(const float4*)&g_xt[(long long)r * OUT_C + cg];
    float* p = outacc + (long long)c * OUT_C + cg;
    atomicAdd(p + 0, v.x * nrm);
    atomicAdd(p + 1, v.y * nrm);
    atomicAdd(p + 2, v.z * nrm);
    atomicAdd(p + 3, v.w * nrm);
}

// ---------------- K5: +bias, PReLU, per-channel sum/sumsq -------------------
__global__ void k_prelu_stats(float* __restrict__ y, const float* __restrict__ bias,
                              const float* __restrict__ pa, int n) {
    int c = threadIdx.x & 63;
    float b = bias[c];
    float a = pa[0];
    float s = 0.0f, q = 0.0f;
    for (int r = blockIdx.x * 4 + (threadIdx.x >> 6); r < n; r += gridDim.x * 4) {
        long long idx = (long long)r * OUT_C + c;
        float v = y[idx] + b;
        v = (v >= 0.0f) ? v : a * v;
        y[idx] = v;
        s += v;
        q = fmaf(v, v, q);
    }
    __shared__ float ss[256], sq[256];
    ss[threadIdx.x] = s; sq[threadIdx.x] = q;
    __syncthreads();
    if (threadIdx.x < 64) {
        s = ss[threadIdx.x] + ss[threadIdx.x + 64] + ss[threadIdx.x + 128] + ss[threadIdx.x + 192];
        q = sq[threadIdx.x] + sq[threadIdx.x + 64] + sq[threadIdx.x + 128] + sq[threadIdx.x + 192];
        atomicAdd(&g_sum[threadIdx.x], s);
        atomicAdd(&g_sumsq[threadIdx.x], q);
    }
}

// ---------------- K6: GraphNorm finalize -------------------------------------
__global__ void k_gnorm(float* __restrict__ y, const float* __restrict__ gw,
                        const float* __restrict__ gb, const float* __restrict__ gms, int n) {
    int c = threadIdx.x & 63;
    float invn = 1.0f / (float)n;
    float m = g_sum[c] * invn;
    float s = gms[c];
    // var = E[v^2] - 2 s m E[v] + s^2 m^2
    float var = fmaf(-2.0f * s * m, m, g_sumsq[c] * invn) + s * s * m * m;
    float inv = rsqrtf(var + 1e-5f);
    float w = gw[c] * inv;
    float sm = s * m;
    float bb = gb[c];
    for (int r = blockIdx.x * 4 + (threadIdx.x >> 6); r < n; r += gridDim.x * 4) {
        long long idx = (long long)r * OUT_C + c;
        y[idx] = fmaf(y[idx] - sm, w, bb);
    }
}

// ---------------- launch -----------------------------------------------------
extern "C" void kernel_launch(void* const* d_in, const int* in_sizes, int n_in,
                              void* d_out, int out_size) {
    const float* x    = (const float*)d_in[0];
    const int*   ei   = (const int*)d_in[1];     // edge_index downcast to int32 by harness
    const float* ea   = (const float*)d_in[2];
    const float* lw   = (const float*)d_in[3];
    const float* bias = (const float*)d_in[4];
    const float* w1   = (const float*)d_in[5];
    const float* b1   = (const float*)d_in[6];
    const float* w2   = (const float*)d_in[7];
    const float* b2   = (const float*)d_in[8];
    const float* pa   = (const float*)d_in[9];
    const float* gw   = (const float*)d_in[10];
    const float* gb   = (const float*)d_in[11];
    const float* gms  = (const float*)d_in[12];
    float* out = (float*)d_out;

    int n = in_sizes[0] / IN_C;   // nodes
    int e = in_sizes[1] / 2;      // edges

    k_init<<<(n + 255) / 256, 256>>>(n);
    k_edge_mlp<<<(e + 255) / 256, 256>>>(ea, w1, b1, w2, b2, ei, e, n);
    k_dinv<<<(n + 255) / 256, 256>>>(n);
    k_xt<<<(n + GR - 1) / GR, 256>>>(x, lw, out, n);
    long long tot = (long long)e * 16;
    k_scatter<<<(unsigned)((tot + 255) / 256), 256>>>(ei, out, e, n);
    k_prelu_stats<<<592, 256>>>(out, bias, pa, n);
    k_gnorm<<<592, 256>>>(out, gw, gb, gms, n);
}

// round 4
// speedup vs baseline: 1.4264x; 1.4264x over previous
#include <cuda_runtime.h>

#define IN_C    128
#define OUT_C   64
#define EDGE_DIM 16
#define EDGE_HID 32
#define NMAX    100000
#define EMAX    1600000
#define GR      64
#define KC      64

// ---------------- scratch (static device globals; no allocations) ----------
static __device__ float g_ew[EMAX];
static __device__ float g_deg[NMAX];
static __device__ float g_dinv[NMAX];
static __device__ float g_xt[(long long)NMAX * OUT_C];
static __device__ float g_sum[OUT_C];
static __device__ float g_sumsq[OUT_C];

// ---------------- K0: init deg=1 (self-loop weight), zero stats ------------
__global__ void k_init(int n) {
    int i = blockIdx.x * blockDim.x + threadIdx.x;
    if (i < n) g_deg[i] = 1.0f;
    if (i < OUT_C) { g_sum[i] = 0.0f; g_sumsq[i] = 0.0f; }
}

// ---------------- K1: edge MLP gate (2 edges/thread) + degree accum ---------
__global__ void k_edge_mlp(const float* __restrict__ ea,
                           const float* __restrict__ w1, const float* __restrict__ b1,
                           const float* __restrict__ w2, const float* __restrict__ b2,
                           const int* __restrict__ ei, int e_, int n) {
    __shared__ __align__(16) float sw1[EDGE_HID * EDGE_DIM];
    __shared__ float sb1[EDGE_HID];
    __shared__ float sw2[EDGE_HID];
    __shared__ float sb2;
    for (int i = threadIdx.x; i < EDGE_HID * EDGE_DIM; i += blockDim.x) sw1[i] = w1[i];
    if (threadIdx.x < EDGE_HID) { sb1[threadIdx.x] = b1[threadIdx.x]; sw2[threadIdx.x] = w2[threadIdx.x]; }
    if (threadIdx.x == 0) sb2 = b2[0];
    __syncthreads();

    int e0 = (blockIdx.x * blockDim.x + threadIdx.x) * 2;
    if (e0 >= e_) return;
    bool two = (e0 + 1) < e_;

    float a0[EDGE_DIM], a1[EDGE_DIM];
    {
        const float4* p = (const float4*)(ea + (long long)e0 * EDGE_DIM);
#pragma unroll
        for (int q = 0; q < 4; q++) {
            float4 v = p[q];
            a0[q*4+0] = v.x; a0[q*4+1] = v.y; a0[q*4+2] = v.z; a0[q*4+3] = v.w;
            float4 u = two ? p[q + 4] : make_float4(0.f,0.f,0.f,0.f);
            a1[q*4+0] = u.x; a1[q*4+1] = u.y; a1[q*4+2] = u.z; a1[q*4+3] = u.w;
        }
    }

    float acc0 = sb2, acc1 = sb2;
#pragma unroll 4
    for (int h = 0; h < EDGE_HID; ++h) {
        float s0 = sb1[h], s1 = s0;
        const float4* wr = (const float4*)&sw1[h * EDGE_DIM];
#pragma unroll
        for (int q = 0; q < 4; ++q) {
            float4 w = wr[q];
            s0 = fmaf(a0[q*4+0], w.x, s0); s0 = fmaf(a0[q*4+1], w.y, s0);
            s0 = fmaf(a0[q*4+2], w.z, s0); s0 = fmaf(a0[q*4+3], w.w, s0);
            s1 = fmaf(a1[q*4+0], w.x, s1); s1 = fmaf(a1[q*4+1], w.y, s1);
            s1 = fmaf(a1[q*4+2], w.z, s1); s1 = fmaf(a1[q*4+3], w.w, s1);
        }
        float w2h = sw2[h];
        acc0 = fmaf(fmaxf(s0, 0.0f), w2h, acc0);
        acc1 = fmaf(fmaxf(s1, 0.0f), w2h, acc1);
    }
    float g0 = 1.0f / (1.0f + __expf(-acc0));
    g_ew[e0] = g0;
    int c0 = ei[e_ + e0];
    if ((unsigned)c0 < (unsigned)n) atomicAdd(&g_deg[c0], g0);
    if (two) {
        float g1 = 1.0f / (1.0f + __expf(-acc1));
        g_ew[e0 + 1] = g1;
        int c1 = ei[e_ + e0 + 1];
        if ((unsigned)c1 < (unsigned)n) atomicAdd(&g_deg[c1], g1);
    }
}

// ---------------- K2: dinv = rsqrt(deg) -------------------------------------
__global__ void k_dinv(int n) {
    int i = blockIdx.x * blockDim.x + threadIdx.x;
    if (i < n) g_dinv[i] = rsqrtf(g_deg[i]);
}

// ---------------- K3: xt = x @ lin_w.T ; out = dinv^2 * xt (self loop) ------
#define XS_PAD 68   // 68*4 = 272 bytes, 16B-aligned rows for float4 LDS
__global__ void k_xt(const float* __restrict__ x, const float* __restrict__ lw,
                     float* __restrict__ outacc, int n) {
    __shared__ __align__(16) float xs[KC][XS_PAD];   // xs[k][row]
    __shared__ __align__(16) float ws[KC][OUT_C];    // ws[k][o]
    int r0 = blockIdx.x * GR;
    int tx = threadIdx.x & 15;
    int ty = threadIdx.x >> 4;
    float acc[4][4] = {};

    for (int k0 = 0; k0 < IN_C; k0 += KC) {
        for (int i = threadIdx.x; i < GR * (KC / 4); i += 256) {
            int r = i >> 4, kq = i & 15;
            float4 v = make_float4(0.f, 0.f, 0.f, 0.f);
            if (r0 + r < n) v = *(const float4*)(x + (long long)(r0 + r) * IN_C + k0 + kq * 4);
            xs[kq * 4 + 0][r] = v.x; xs[kq * 4 + 1][r] = v.y;
            xs[kq * 4 + 2][r] = v.z; xs[kq * 4 + 3][r] = v.w;
        }
        for (int i = threadIdx.x; i < OUT_C * (KC / 4); i += 256) {
            int o = i >> 4, kq = i & 15;
            float4 v = *(const float4*)(lw + (long long)o * IN_C + k0 + kq * 4);
            ws[kq * 4 + 0][o] = v.x; ws[kq * 4 + 1][o] = v.y;
            ws[kq * 4 + 2][o] = v.z; ws[kq * 4 + 3][o] = v.w;
        }
        __syncthreads();
#pragma unroll 8
        for (int k = 0; k < KC; ++k) {
            float4 bv = *(const float4*)&ws[k][tx * 4];
            float4 av = *(const float4*)&xs[k][ty * 4];
            acc[0][0] = fmaf(av.x, bv.x, acc[0][0]); acc[0][1] = fmaf(av.x, bv.y, acc[0][1]);
            acc[0][2] = fmaf(av.x, bv.z, acc[0][2]); acc[0][3] = fmaf(av.x, bv.w, acc[0][3]);
            acc[1][0] = fmaf(av.y, bv.x, acc[1][0]); acc[1][1] = fmaf(av.y, bv.y, acc[1][1]);
            acc[1][2] = fmaf(av.y, bv.z, acc[1][2]); acc[1][3] = fmaf(av.y, bv.w, acc[1][3]);
            acc[2][0] = fmaf(av.z, bv.x, acc[2][0]); acc[2][1] = fmaf(av.z, bv.y, acc[2][1]);
            acc[2][2] = fmaf(av.z, bv.z, acc[2][2]); acc[2][3] = fmaf(av.z, bv.w, acc[2][3]);
            acc[3][0] = fmaf(av.w, bv.x, acc[3][0]); acc[3][1] = fmaf(av.w, bv.y, acc[3][1]);
            acc[3][2] = fmaf(av.w, bv.z, acc[3][2]); acc[3][3] = fmaf(av.w, bv.w, acc[3][3]);
        }
        __syncthreads();
    }
#pragma unroll
    for (int i = 0; i < 4; ++i) {
        int r = r0 + ty * 4 + i;
        if (r < n) {
            float d = g_dinv[r];
            float d2 = d * d;
            float4 o = make_float4(acc[i][0], acc[i][1], acc[i][2], acc[i][3]);
            *(float4*)&g_xt[(long long)r * OUT_C + tx * 4] = o;
            float4 s = make_float4(o.x * d2, o.y * d2, o.z * d2, o.w * d2);
            *(float4*)(outacc + (long long)r * OUT_C + tx * 4) = s;
        }
    }
}

// ---------------- K4: scatter messages (16 threads/edge, v4 reductions) -----
__global__ void k_scatter(const int* __restrict__ ei, float* __restrict__ outacc, int e_, int n) {
    long long gid = (long long)blockIdx.x * blockDim.x + threadIdx.x;
    int e = (int)(gid >> 4);
    if (e >= e_) return;
    int cg = ((int)gid & 15) * 4;
    int r = ei[e];
    int c = ei[e_ + e];
    if ((unsigned)r >= (unsigned)n || (unsigned)c >= (unsigned)n) return;
    float nrm = g_dinv[r] * g_ew[e] * g_dinv[c];
    float4 v = *(const float4*)&g_xt[(long long)r * OUT_C + cg];
    float* p = outacc + (long long)c * OUT_C + cg;
    asm volatile("red.global.add.v4.f32 [%0], {%1, %2, %3, %4};"
                 :: "l"(p), "f"(v.x * nrm), "f"(v.y * nrm), "f"(v.z * nrm), "f"(v.w * nrm)
                 : "memory");
}

// ---------------- K5: +bias, PReLU, per-channel sum/sumsq -------------------
__global__ void k_prelu_stats(float* __restrict__ y, const float* __restrict__ bias,
                              const float* __restrict__ pa, int n) {
    int c = threadIdx.x & 63;
    float b = bias[c];
    float a = pa[0];
    float s = 0.0f, q = 0.0f;
    for (int r = blockIdx.x * 4 + (threadIdx.x >> 6); r < n; r += gridDim.x * 4) {
        long long idx = (long long)r * OUT_C + c;
        float v = y[idx] + b;
        v = (v >= 0.0f) ? v : a * v;
        y[idx] = v;
        s += v;
        q = fmaf(v, v, q);
    }
    __shared__ float ss[256], sq[256];
    ss[threadIdx.x] = s; sq[threadIdx.x] = q;
    __syncthreads();
    if (threadIdx.x < 64) {
        s = ss[threadIdx.x] + ss[threadIdx.x + 64] + ss[threadIdx.x + 128] + ss[threadIdx.x + 192];
        q = sq[threadIdx.x] + sq[threadIdx.x + 64] + sq[threadIdx.x + 128] + sq[threadIdx.x + 192];
        atomicAdd(&g_sum[threadIdx.x], s);
        atomicAdd(&g_sumsq[threadIdx.x], q);
    }
}

// ---------------- K6: GraphNorm finalize -------------------------------------
__global__ void k_gnorm(float* __restrict__ y, const float* __restrict__ gw,
                        const float* __restrict__ gb, const float* __restrict__ gms, int n) {
    int c = threadIdx.x & 63;
    float invn = 1.0f / (float)n;
    float m = g_sum[c] * invn;
    float s = gms[c];
    float var = fmaf(-2.0f * s * m, m, g_sumsq[c] * invn) + s * s * m * m;
    float inv = rsqrtf(var + 1e-5f);
    float w = gw[c] * inv;
    float sm = s * m;
    float bb = gb[c];
    for (int r = blockIdx.x * 4 + (threadIdx.x >> 6); r < n; r += gridDim.x * 4) {
        long long idx = (long long)r * OUT_C + c;
        y[idx] = fmaf(y[idx] - sm, w, bb);
    }
}

// ---------------- launch -----------------------------------------------------
extern "C" void kernel_launch(void* const* d_in, const int* in_sizes, int n_in,
                              void* d_out, int out_size) {
    const float* x    = (const float*)d_in[0];
    const int*   ei   = (const int*)d_in[1];     // edge_index downcast to int32 by harness
    const float* ea   = (const float*)d_in[2];
    const float* lw   = (const float*)d_in[3];
    const float* bias = (const float*)d_in[4];
    const float* w1   = (const float*)d_in[5];
    const float* b1   = (const float*)d_in[6];
    const float* w2   = (const float*)d_in[7];
    const float* b2   = (const float*)d_in[8];
    const float* pa   = (const float*)d_in[9];
    const float* gw   = (const float*)d_in[10];
    const float* gb   = (const float*)d_in[11];
    const float* gms  = (const float*)d_in[12];
    float* out = (float*)d_out;

    int n = in_sizes[0] / IN_C;   // nodes
    int e = in_sizes[1] / 2;      // edges

    k_init<<<(n + 255) / 256, 256>>>(n);
    int th_mlp = (e + 1) / 2;
    k_edge_mlp<<<(th_mlp + 255) / 256, 256>>>(ea, w1, b1, w2, b2, ei, e, n);
    k_dinv<<<(n + 255) / 256, 256>>>(n);
    k_xt<<<(n + GR - 1) / GR, 256>>>(x, lw, out, n);
    long long tot = (long long)e * 16;
    k_scatter<<<(unsigned)((tot + 255) / 256), 256>>>(ei, out, e, n);
    k_prelu_stats<<<592, 256>>>(out, bias, pa, n);
    k_gnorm<<<592, 256>>>(out, gw, gb, gms, n);
}

// round 5
// speedup vs baseline: 1.5216x; 1.0668x over previous
#include <cuda_runtime.h>

#define IN_C    128
#define OUT_C   64
#define EDGE_DIM 16
#define EDGE_HID 32
#define NMAX    100000
#define EMAX    1600000

typedef unsigned long long u64;

__device__ __forceinline__ u64 pk(float lo, float hi) {
    u64 r; asm("mov.b64 %0, {%1,%2};" : "=l"(r) : "f"(lo), "f"(hi)); return r;
}
__device__ __forceinline__ void upk(u64 v, float& lo, float& hi) {
    asm("mov.b64 {%0,%1}, %2;" : "=f"(lo), "=f"(hi) : "l"(v));
}
__device__ __forceinline__ void fma2(u64& d, u64 a, u64 b) {
    asm("fma.rn.f32x2 %0, %1, %2, %0;" : "+l"(d) : "l"(a), "l"(b));
}

// ---------------- scratch ----------------------------------------------------
static __device__ float g_ew[EMAX];
static __device__ float g_deg[NMAX];
static __device__ float g_dinv[NMAX];
static __device__ float g_xt[(long long)NMAX * OUT_C];
static __device__ float g_sum[OUT_C];
static __device__ float g_sumsq[OUT_C];

// ---------------- K0 ---------------------------------------------------------
__global__ void k_init(int n) {
    int i = blockIdx.x * blockDim.x + threadIdx.x;
    if (i < n) g_deg[i] = 1.0f;
    if (i < OUT_C) { g_sum[i] = 0.0f; g_sumsq[i] = 0.0f; }
}

// ---------------- K1: edge MLP, f32x2 over h-pairs, 2 edges/thread ----------
__global__ void k_edge_mlp(const float* __restrict__ ea,
                           const float* __restrict__ w1, const float* __restrict__ b1,
                           const float* __restrict__ w2, const float* __restrict__ b2,
                           const int* __restrict__ ei, int e_, int n) {
    // swp[p*16+i] = (w1[2p][i], w1[2p+1][i])  -> LDS.128 gives 2 f32x2 operands
    __shared__ __align__(16) float2 swp[16 * 16];
    __shared__ __align__(8)  float2 sb1p[16];
    __shared__ float sw2[EDGE_HID];
    __shared__ float sb2;
    {
        int t = threadIdx.x;
        if (t < 256) {
            int p = t >> 4, i = t & 15;
            swp[t] = make_float2(w1[(2 * p) * EDGE_DIM + i], w1[(2 * p + 1) * EDGE_DIM + i]);
        }
        if (t < 16) sb1p[t] = make_float2(b1[2 * t], b1[2 * t + 1]);
        if (t < EDGE_HID) sw2[t] = w2[t];
        if (t == 0) sb2 = b2[0];
    }
    __syncthreads();

    int e0 = (blockIdx.x * blockDim.x + threadIdx.x) * 2;
    if (e0 >= e_) return;
    bool two = (e0 + 1) < e_;

    u64 a0p[EDGE_DIM], a1p[EDGE_DIM];
    {
        const float4* p = (const float4*)(ea + (long long)e0 * EDGE_DIM);
#pragma unroll
        for (int q = 0; q < 4; q++) {
            float4 v = p[q];
            a0p[q*4+0] = pk(v.x, v.x); a0p[q*4+1] = pk(v.y, v.y);
            a0p[q*4+2] = pk(v.z, v.z); a0p[q*4+3] = pk(v.w, v.w);
            float4 u = two ? p[q + 4] : make_float4(0.f, 0.f, 0.f, 0.f);
            a1p[q*4+0] = pk(u.x, u.x); a1p[q*4+1] = pk(u.y, u.y);
            a1p[q*4+2] = pk(u.z, u.z); a1p[q*4+3] = pk(u.w, u.w);
        }
    }

    float acc0 = sb2, acc1 = sb2;
#pragma unroll 4
    for (int p = 0; p < 16; ++p) {
        float2 sb = sb1p[p];
        u64 s0 = pk(sb.x, sb.y);
        u64 s1 = s0;
#pragma unroll
        for (int iq = 0; iq < 8; ++iq) {
            ulonglong2 w = *(const ulonglong2*)&swp[p * 16 + iq * 2];
            fma2(s0, a0p[iq*2],   w.x);
            fma2(s0, a0p[iq*2+1], w.y);
            fma2(s1, a1p[iq*2],   w.x);
            fma2(s1, a1p[iq*2+1], w.y);
        }
        float wlo = sw2[2*p], whi = sw2[2*p+1];
        float t0, t1;
        upk(s0, t0, t1);
        acc0 = fmaf(fmaxf(t0, 0.f), wlo, fmaf(fmaxf(t1, 0.f), whi, acc0));
        upk(s1, t0, t1);
        acc1 = fmaf(fmaxf(t0, 0.f), wlo, fmaf(fmaxf(t1, 0.f), whi, acc1));
    }
    float g0 = 1.0f / (1.0f + __expf(-acc0));
    g_ew[e0] = g0;
    int c0 = ei[e_ + e0];
    if ((unsigned)c0 < (unsigned)n) atomicAdd(&g_deg[c0], g0);
    if (two) {
        float g1 = 1.0f / (1.0f + __expf(-acc1));
        g_ew[e0 + 1] = g1;
        int c1 = ei[e_ + e0 + 1];
        if ((unsigned)c1 < (unsigned)n) atomicAdd(&g_deg[c1], g1);
    }
}

// ---------------- K2 ---------------------------------------------------------
__global__ void k_dinv(int n) {
    int i = blockIdx.x * blockDim.x + threadIdx.x;
    if (i < n) g_dinv[i] = rsqrtf(g_deg[i]);
}

// ---------------- K3: xt = x @ lin_w.T, 8x8 tile, f32x2 (row pairs) ----------
#define GR 256
#define KC 32
#define XROW 260   // 260*4 = 1040 bytes, 16B multiple
__global__ void k_xt(const float* __restrict__ x, const float* __restrict__ lw,
                     float* __restrict__ outacc, int n) {
    __shared__ __align__(16) float xs[KC][XROW];
    __shared__ __align__(16) float ws[KC][OUT_C];
    int r0 = blockIdx.x * GR;
    int tx = threadIdx.x & 7;        // 8 col-groups
    int ty = threadIdx.x >> 3;       // 32 row-groups of 8
    u64 accp[4][8] = {};             // (row-pair, col): lo=row 2rp, hi=row 2rp+1

    for (int k0 = 0; k0 < IN_C; k0 += KC) {
        for (int i = threadIdx.x; i < GR * (KC / 4); i += 256) {
            int r = i >> 3, kq = i & 7;
            float4 v = make_float4(0.f, 0.f, 0.f, 0.f);
            if (r0 + r < n) v = *(const float4*)(x + (long long)(r0 + r) * IN_C + k0 + kq * 4);
            xs[kq*4+0][r] = v.x; xs[kq*4+1][r] = v.y;
            xs[kq*4+2][r] = v.z; xs[kq*4+3][r] = v.w;
        }
        for (int i = threadIdx.x; i < OUT_C * (KC / 4); i += 256) {
            int o = i >> 3, kq = i & 7;
            float4 v = *(const float4*)(lw + (long long)o * IN_C + k0 + kq * 4);
            ws[kq*4+0][o] = v.x; ws[kq*4+1][o] = v.y;
            ws[kq*4+2][o] = v.z; ws[kq*4+3][o] = v.w;
        }
        __syncthreads();
#pragma unroll 8
        for (int k = 0; k < KC; ++k) {
            float4 a0 = *(const float4*)&xs[k][ty * 8];
            float4 a1 = *(const float4*)&xs[k][ty * 8 + 4];
            float4 b0 = *(const float4*)&ws[k][tx * 8];
            float4 b1 = *(const float4*)&ws[k][tx * 8 + 4];
            u64 ap0 = pk(a0.x, a0.y), ap1 = pk(a0.z, a0.w);
            u64 ap2 = pk(a1.x, a1.y), ap3 = pk(a1.z, a1.w);
            float bb[8] = {b0.x, b0.y, b0.z, b0.w, b1.x, b1.y, b1.z, b1.w};
#pragma unroll
            for (int j = 0; j < 8; ++j) {
                u64 bj = pk(bb[j], bb[j]);
                fma2(accp[0][j], ap0, bj);
                fma2(accp[1][j], ap1, bj);
                fma2(accp[2][j], ap2, bj);
                fma2(accp[3][j], ap3, bj);
            }
        }
        __syncthreads();
    }
    // epilogue: unpack row pairs, write g_xt and self-loop-scaled out
#pragma unroll
    for (int rp = 0; rp < 4; ++rp) {
        float lo[8], hi[8];
#pragma unroll
        for (int j = 0; j < 8; ++j) upk(accp[rp][j], lo[j], hi[j]);
        int rA = r0 + ty * 8 + rp * 2;
        int rB = rA + 1;
        if (rA < n) {
            float d = g_dinv[rA]; float d2 = d * d;
            float4 o0 = make_float4(lo[0], lo[1], lo[2], lo[3]);
            float4 o1 = make_float4(lo[4], lo[5], lo[6], lo[7]);
            long long base = (long long)rA * OUT_C + tx * 8;
            *(float4*)&g_xt[base] = o0; *(float4*)&g_xt[base + 4] = o1;
            *(float4*)(outacc + base)     = make_float4(o0.x*d2, o0.y*d2, o0.z*d2, o0.w*d2);
            *(float4*)(outacc + base + 4) = make_float4(o1.x*d2, o1.y*d2, o1.z*d2, o1.w*d2);
        }
        if (rB < n) {
            float d = g_dinv[rB]; float d2 = d * d;
            float4 o0 = make_float4(hi[0], hi[1], hi[2], hi[3]);
            float4 o1 = make_float4(hi[4], hi[5], hi[6], hi[7]);
            long long base = (long long)rB * OUT_C + tx * 8;
            *(float4*)&g_xt[base] = o0; *(float4*)&g_xt[base + 4] = o1;
            *(float4*)(outacc + base)     = make_float4(o0.x*d2, o0.y*d2, o0.z*d2, o0.w*d2);
            *(float4*)(outacc + base + 4) = make_float4(o1.x*d2, o1.y*d2, o1.z*d2, o1.w*d2);
        }
    }
}

// ---------------- K4: scatter (16 threads/edge, v4 RED) ----------------------
__global__ void k_scatter(const int* __restrict__ ei, float* __restrict__ outacc, int e_, int n) {
    long long gid = (long long)blockIdx.x * blockDim.x + threadIdx.x;
    int e = (int)(gid >> 4);
    if (e >= e_) return;
    int cg = ((int)gid & 15) * 4;
    int r = ei[e];
    int c = ei[e_ + e];
    if ((unsigned)r >= (unsigned)n || (unsigned)c >= (unsigned)n) return;
    float nrm = g_dinv[r] * g_ew[e] * g_dinv[c];
    float4 v = *(const float4*)&g_xt[(long long)r * OUT_C + cg];
    float* p = outacc + (long long)c * OUT_C + cg;
    asm volatile("red.global.add.v4.f32 [%0], {%1, %2, %3, %4};"
                 :: "l"(p), "f"(v.x * nrm), "f"(v.y * nrm), "f"(v.z * nrm), "f"(v.w * nrm)
                 : "memory");
}

// ---------------- K5: +bias, PReLU, per-channel sum/sumsq --------------------
__global__ void k_prelu_stats(float* __restrict__ y, const float* __restrict__ bias,
                              const float* __restrict__ pa, int n) {
    int c = threadIdx.x & 63;
    float b = bias[c];
    float a = pa[0];
    float s = 0.0f, q = 0.0f;
    for (int r = blockIdx.x * 4 + (threadIdx.x >> 6); r < n; r += gridDim.x * 4) {
        long long idx = (long long)r * OUT_C + c;
        float v = y[idx] + b;
        v = (v >= 0.0f) ? v : a * v;
        y[idx] = v;
        s += v;
        q = fmaf(v, v, q);
    }
    __shared__ float ss[256], sq[256];
    ss[threadIdx.x] = s; sq[threadIdx.x] = q;
    __syncthreads();
    if (threadIdx.x < 64) {
        s = ss[threadIdx.x] + ss[threadIdx.x + 64] + ss[threadIdx.x + 128] + ss[threadIdx.x + 192];
        q = sq[threadIdx.x] + sq[threadIdx.x + 64] + sq[threadIdx.x + 128] + sq[threadIdx.x + 192];
        atomicAdd(&g_sum[threadIdx.x], s);
        atomicAdd(&g_sumsq[threadIdx.x], q);
    }
}

// ---------------- K6: GraphNorm finalize --------------------------------------
__global__ void k_gnorm(float* __restrict__ y, const float* __restrict__ gw,
                        const float* __restrict__ gb, const float* __restrict__ gms, int n) {
    int c = threadIdx.x & 63;
    float invn = 1.0f / (float)n;
    float m = g_sum[c] * invn;
    float s = gms[c];
    float var = fmaf(-2.0f * s * m, m, g_sumsq[c] * invn) + s * s * m * m;
    float inv = rsqrtf(var + 1e-5f);
    float w = gw[c] * inv;
    float sm = s * m;
    float bb = gb[c];
    for (int r = blockIdx.x * 4 + (threadIdx.x >> 6); r < n; r += gridDim.x * 4) {
        long long idx = (long long)r * OUT_C + c;
        y[idx] = fmaf(y[idx] - sm, w, bb);
    }
}

// ---------------- launch -------------------------------------------------------
extern "C" void kernel_launch(void* const* d_in, const int* in_sizes, int n_in,
                              void* d_out, int out_size) {
    const float* x    = (const float*)d_in[0];
    const int*   ei   = (const int*)d_in[1];
    const float* ea   = (const float*)d_in[2];
    const float* lw   = (const float*)d_in[3];
    const float* bias = (const float*)d_in[4];
    const float* w1   = (const float*)d_in[5];
    const float* b1   = (const float*)d_in[6];
    const float* w2   = (const float*)d_in[7];
    const float* b2   = (const float*)d_in[8];
    const float* pa   = (const float*)d_in[9];
    const float* gw   = (const float*)d_in[10];
    const float* gb   = (const float*)d_in[11];
    const float* gms  = (const float*)d_in[12];
    float* out = (float*)d_out;

    int n = in_sizes[0] / IN_C;
    int e = in_sizes[1] / 2;

    k_init<<<(n + 255) / 256, 256>>>(n);
    int th_mlp = (e + 1) / 2;
    k_edge_mlp<<<(th_mlp + 255) / 256, 256>>>(ea, w1, b1, w2, b2, ei, e, n);
    k_dinv<<<(n + 255) / 256, 256>>>(n);
    k_xt<<<(n + GR - 1) / GR, 256>>>(x, lw, out, n);
    long long tot = (long long)e * 16;
    k_scatter<<<(unsigned)((tot + 255) / 256), 256>>>(ei, out, e, n);
    k_prelu_stats<<<592, 256>>>(out, bias, pa, n);
    k_gnorm<<<592, 256>>>(out, gw, gb, gms, n);
}

// round 6
// speedup vs baseline: 1.6575x; 1.0893x over previous
#include <cuda_runtime.h>

#define IN_C    128
#define OUT_C   64
#define EDGE_DIM 16
#define EDGE_HID 32
#define NMAX    100000
#define EMAX    1600000

typedef unsigned long long u64;

__device__ __forceinline__ u64 pk(float lo, float hi) {
    u64 r; asm("mov.b64 %0, {%1,%2};" : "=l"(r) : "f"(lo), "f"(hi)); return r;
}
__device__ __forceinline__ void upk(u64 v, float& lo, float& hi) {
    asm("mov.b64 {%0,%1}, %2;" : "=f"(lo), "=f"(hi) : "l"(v));
}
__device__ __forceinline__ void fma2(u64& d, u64 a, u64 b) {
    asm("fma.rn.f32x2 %0, %1, %2, %0;" : "+l"(d) : "l"(a), "l"(b));
}

// ---------------- scratch ----------------------------------------------------
static __device__ float g_ew[EMAX];
static __device__ float g_deg[NMAX];
static __device__ float g_dinv[NMAX];
static __device__ float g_xt[(long long)NMAX * OUT_C];
static __device__ float g_sum[OUT_C];
static __device__ float g_sumsq[OUT_C];

// ---------------- K0: init deg=1 (self loop), zero stats ---------------------
__global__ void k_init(int n) {
    int i = blockIdx.x * blockDim.x + threadIdx.x;
    if (i < n) g_deg[i] = 1.0f;
    if (i < OUT_C) { g_sum[i] = 0.0f; g_sumsq[i] = 0.0f; }
}

// ---------------- K1: edge MLP, f32x2 over h-pairs, 2 edges/thread -----------
__global__ void k_edge_mlp(const float* __restrict__ ea,
                           const float* __restrict__ w1, const float* __restrict__ b1,
                           const float* __restrict__ w2, const float* __restrict__ b2,
                           const int* __restrict__ ei, int e_, int n) {
    __shared__ __align__(16) float2 swp[16 * 16];
    __shared__ __align__(8)  float2 sb1p[16];
    __shared__ float sw2[EDGE_HID];
    __shared__ float sb2;
    {
        int t = threadIdx.x;
        if (t < 256) {
            int p = t >> 4, i = t & 15;
            swp[t] = make_float2(w1[(2 * p) * EDGE_DIM + i], w1[(2 * p + 1) * EDGE_DIM + i]);
        }
        if (t < 16) sb1p[t] = make_float2(b1[2 * t], b1[2 * t + 1]);
        if (t < EDGE_HID) sw2[t] = w2[t];
        if (t == 0) sb2 = b2[0];
    }
    __syncthreads();

    int e0 = (blockIdx.x * blockDim.x + threadIdx.x) * 2;
    if (e0 >= e_) return;
    bool two = (e0 + 1) < e_;

    u64 a0p[EDGE_DIM], a1p[EDGE_DIM];
    {
        const float4* p = (const float4*)(ea + (long long)e0 * EDGE_DIM);
#pragma unroll
        for (int q = 0; q < 4; q++) {
            float4 v = p[q];
            a0p[q*4+0] = pk(v.x, v.x); a0p[q*4+1] = pk(v.y, v.y);
            a0p[q*4+2] = pk(v.z, v.z); a0p[q*4+3] = pk(v.w, v.w);
            float4 u = two ? p[q + 4] : make_float4(0.f, 0.f, 0.f, 0.f);
            a1p[q*4+0] = pk(u.x, u.x); a1p[q*4+1] = pk(u.y, u.y);
            a1p[q*4+2] = pk(u.z, u.z); a1p[q*4+3] = pk(u.w, u.w);
        }
    }

    float acc0 = sb2, acc1 = sb2;
#pragma unroll 4
    for (int p = 0; p < 16; ++p) {
        float2 sb = sb1p[p];
        u64 s0 = pk(sb.x, sb.y);
        u64 s1 = s0;
#pragma unroll
        for (int iq = 0; iq < 8; ++iq) {
            ulonglong2 w = *(const ulonglong2*)&swp[p * 16 + iq * 2];
            fma2(s0, a0p[iq*2],   w.x);
            fma2(s0, a0p[iq*2+1], w.y);
            fma2(s1, a1p[iq*2],   w.x);
            fma2(s1, a1p[iq*2+1], w.y);
        }
        float wlo = sw2[2*p], whi = sw2[2*p+1];
        float t0, t1;
        upk(s0, t0, t1);
        acc0 = fmaf(fmaxf(t0, 0.f), wlo, fmaf(fmaxf(t1, 0.f), whi, acc0));
        upk(s1, t0, t1);
        acc1 = fmaf(fmaxf(t0, 0.f), wlo, fmaf(fmaxf(t1, 0.f), whi, acc1));
    }
    float g0 = 1.0f / (1.0f + __expf(-acc0));
    g_ew[e0] = g0;
    int c0 = ei[e_ + e0];
    if ((unsigned)c0 < (unsigned)n) atomicAdd(&g_deg[c0], g0);
    if (two) {
        float g1 = 1.0f / (1.0f + __expf(-acc1));
        g_ew[e0 + 1] = g1;
        int c1 = ei[e_ + e0 + 1];
        if ((unsigned)c1 < (unsigned)n) atomicAdd(&g_deg[c1], g1);
    }
}

// ---------------- K3: xt = x @ lin_w.T (pure; no deg dependency) -------------
// 8 rows x 4 cols per thread, 3 CTAs/SM target
#define GR 128
#define KC 32
#define XROW 132   // 132*4 = 528 bytes, 16B multiple
__global__ void __launch_bounds__(256, 3)
k_xt(const float* __restrict__ x, const float* __restrict__ lw, int n) {
    __shared__ __align__(16) float xs[KC][XROW];
    __shared__ __align__(16) float ws[KC][OUT_C];
    int r0 = blockIdx.x * GR;
    int tx = threadIdx.x & 15;       // 16 col-groups of 4
    int ty = threadIdx.x >> 4;       // 16 row-groups of 8
    u64 accp[4][4] = {};             // [row-pair][col]

    for (int k0 = 0; k0 < IN_C; k0 += KC) {
        for (int i = threadIdx.x; i < GR * (KC / 4); i += 256) {
            int r = i >> 3, kq = i & 7;
            float4 v = make_float4(0.f, 0.f, 0.f, 0.f);
            if (r0 + r < n) v = *(const float4*)(x + (long long)(r0 + r) * IN_C + k0 + kq * 4);
            xs[kq*4+0][r] = v.x; xs[kq*4+1][r] = v.y;
            xs[kq*4+2][r] = v.z; xs[kq*4+3][r] = v.w;
        }
        for (int i = threadIdx.x; i < OUT_C * (KC / 4); i += 256) {
            int o = i >> 3, kq = i & 7;
            float4 v = *(const float4*)(lw + (long long)o * IN_C + k0 + kq * 4);
            ws[kq*4+0][o] = v.x; ws[kq*4+1][o] = v.y;
            ws[kq*4+2][o] = v.z; ws[kq*4+3][o] = v.w;
        }
        __syncthreads();
#pragma unroll 8
        for (int k = 0; k < KC; ++k) {
            float4 a0 = *(const float4*)&xs[k][ty * 8];
            float4 a1 = *(const float4*)&xs[k][ty * 8 + 4];
            float4 b  = *(const float4*)&ws[k][tx * 4];
            u64 ap0 = pk(a0.x, a0.y), ap1 = pk(a0.z, a0.w);
            u64 ap2 = pk(a1.x, a1.y), ap3 = pk(a1.z, a1.w);
            u64 b0 = pk(b.x, b.x), b1 = pk(b.y, b.y), b2 = pk(b.z, b.z), b3 = pk(b.w, b.w);
            fma2(accp[0][0], ap0, b0); fma2(accp[0][1], ap0, b1);
            fma2(accp[0][2], ap0, b2); fma2(accp[0][3], ap0, b3);
            fma2(accp[1][0], ap1, b0); fma2(accp[1][1], ap1, b1);
            fma2(accp[1][2], ap1, b2); fma2(accp[1][3], ap1, b3);
            fma2(accp[2][0], ap2, b0); fma2(accp[2][1], ap2, b1);
            fma2(accp[2][2], ap2, b2); fma2(accp[2][3], ap2, b3);
            fma2(accp[3][0], ap3, b0); fma2(accp[3][1], ap3, b1);
            fma2(accp[3][2], ap3, b2); fma2(accp[3][3], ap3, b3);
        }
        __syncthreads();
    }
#pragma unroll
    for (int rp = 0; rp < 4; ++rp) {
        float lo[4], hi[4];
#pragma unroll
        for (int j = 0; j < 4; ++j) upk(accp[rp][j], lo[j], hi[j]);
        int rA = r0 + ty * 8 + rp * 2;
        int rB = rA + 1;
        if (rA < n)
            *(float4*)&g_xt[(long long)rA * OUT_C + tx * 4] = make_float4(lo[0], lo[1], lo[2], lo[3]);
        if (rB < n)
            *(float4*)&g_xt[(long long)rB * OUT_C + tx * 4] = make_float4(hi[0], hi[1], hi[2], hi[3]);
    }
}

// ---------------- K3b: dinv + self-loop init of out ---------------------------
__global__ void k_self(float* __restrict__ outacc, int n) {
    long long gid = (long long)blockIdx.x * blockDim.x + threadIdx.x;
    int r = (int)(gid >> 4);
    if (r >= n) return;
    int cg = ((int)gid & 15) * 4;
    float d = rsqrtf(g_deg[r]);
    if ((gid & 15) == 0) g_dinv[r] = d;
    float d2 = d * d;
    long long base = (long long)r * OUT_C + cg;
    float4 v = *(const float4*)&g_xt[base];
    *(float4*)(outacc + base) = make_float4(v.x * d2, v.y * d2, v.z * d2, v.w * d2);
}

// ---------------- K4: scatter (16 threads/edge, v4 RED) ----------------------
__global__ void k_scatter(const int* __restrict__ ei, float* __restrict__ outacc, int e_, int n) {
    long long gid = (long long)blockIdx.x * blockDim.x + threadIdx.x;
    int e = (int)(gid >> 4);
    if (e >= e_) return;
    int cg = ((int)gid & 15) * 4;
    int r = ei[e];
    int c = ei[e_ + e];
    if ((unsigned)r >= (unsigned)n || (unsigned)c >= (unsigned)n) return;
    float nrm = g_dinv[r] * g_ew[e] * g_dinv[c];
    float4 v = *(const float4*)&g_xt[(long long)r * OUT_C + cg];
    float* p = outacc + (long long)c * OUT_C + cg;
    asm volatile("red.global.add.v4.f32 [%0], {%1, %2, %3, %4};"
                 :: "l"(p), "f"(v.x * nrm), "f"(v.y * nrm), "f"(v.z * nrm), "f"(v.w * nrm)
                 : "memory");
}

// ---------------- K5: +bias, PReLU, per-channel sum/sumsq --------------------
__global__ void k_prelu_stats(float* __restrict__ y, const float* __restrict__ bias,
                              const float* __restrict__ pa, int n) {
    int c = threadIdx.x & 63;
    float b = bias[c];
    float a = pa[0];
    float s = 0.0f, q = 0.0f;
    for (int r = blockIdx.x * 4 + (threadIdx.x >> 6); r < n; r += gridDim.x * 4) {
        long long idx = (long long)r * OUT_C + c;
        float v = y[idx] + b;
        v = (v >= 0.0f) ? v : a * v;
        y[idx] = v;
        s += v;
        q = fmaf(v, v, q);
    }
    __shared__ float ss[256], sq[256];
    ss[threadIdx.x] = s; sq[threadIdx.x] = q;
    __syncthreads();
    if (threadIdx.x < 64) {
        s = ss[threadIdx.x] + ss[threadIdx.x + 64] + ss[threadIdx.x + 128] + ss[threadIdx.x + 192];
        q = sq[threadIdx.x] + sq[threadIdx.x + 64] + sq[threadIdx.x + 128] + sq[threadIdx.x + 192];
        atomicAdd(&g_sum[threadIdx.x], s);
        atomicAdd(&g_sumsq[threadIdx.x], q);
    }
}

// ---------------- K6: GraphNorm finalize --------------------------------------
__global__ void k_gnorm(float* __restrict__ y, const float* __restrict__ gw,
                        const float* __restrict__ gb, const float* __restrict__ gms, int n) {
    int c = threadIdx.x & 63;
    float invn = 1.0f / (float)n;
    float m = g_sum[c] * invn;
    float s = gms[c];
    float var = fmaf(-2.0f * s * m, m, g_sumsq[c] * invn) + s * s * m * m;
    float inv = rsqrtf(var + 1e-5f);
    float w = gw[c] * inv;
    float sm = s * m;
    float bb = gb[c];
    for (int r = blockIdx.x * 4 + (threadIdx.x >> 6); r < n; r += gridDim.x * 4) {
        long long idx = (long long)r * OUT_C + c;
        y[idx] = fmaf(y[idx] - sm, w, bb);
    }
}

// ---------------- launch -------------------------------------------------------
extern "C" void kernel_launch(void* const* d_in, const int* in_sizes, int n_in,
                              void* d_out, int out_size) {
    const float* x    = (const float*)d_in[0];
    const int*   ei   = (const int*)d_in[1];
    const float* ea   = (const float*)d_in[2];
    const float* lw   = (const float*)d_in[3];
    const float* bias = (const float*)d_in[4];
    const float* w1   = (const float*)d_in[5];
    const float* b1   = (const float*)d_in[6];
    const float* w2   = (const float*)d_in[7];
    const float* b2   = (const float*)d_in[8];
    const float* pa   = (const float*)d_in[9];
    const float* gw   = (const float*)d_in[10];
    const float* gb   = (const float*)d_in[11];
    const float* gms  = (const float*)d_in[12];
    float* out = (float*)d_out;

    int n = in_sizes[0] / IN_C;
    int e = in_sizes[1] / 2;

    // one-time side stream + events for graph fork-join (host-side resources,
    // created outside capture on the first (correctness) call)
    static cudaStream_t s1 = nullptr;
    static cudaEvent_t evFork = nullptr, evJoin = nullptr;
    if (s1 == nullptr) {
        cudaStreamCreateWithFlags(&s1, cudaStreamNonBlocking);
        cudaEventCreateWithFlags(&evFork, cudaEventDisableTiming);
        cudaEventCreateWithFlags(&evJoin, cudaEventDisableTiming);
    }

    // fork: k_xt (independent of graph topology) runs on s1 in parallel with
    // init + edge_mlp on the main (capture-origin) stream
    cudaEventRecord(evFork, 0);
    cudaStreamWaitEvent(s1, evFork, 0);
    k_xt<<<(n + GR - 1) / GR, 256, 0, s1>>>(x, lw, n);
    cudaEventRecord(evJoin, s1);

    k_init<<<(n + 255) / 256, 256>>>(n);
    int th_mlp = (e + 1) / 2;
    k_edge_mlp<<<(th_mlp + 255) / 256, 256>>>(ea, w1, b1, w2, b2, ei, e, n);

    // join
    cudaStreamWaitEvent(0, evJoin, 0);

    long long nt = (long long)n * 16;
    k_self<<<(unsigned)((nt + 255) / 256), 256>>>(out, n);
    long long tot = (long long)e * 16;
    k_scatter<<<(unsigned)((tot + 255) / 256), 256>>>(ei, out, e, n);
    k_prelu_stats<<<592, 256>>>(out, bias, pa, n);
    k_gnorm<<<592, 256>>>(out, gw, gb, gms, n);
}

// round 7
// speedup vs baseline: 1.7477x; 1.0544x over previous
#include <cuda_runtime.h>

#define IN_C    128
#define OUT_C   64
#define EDGE_DIM 16
#define EDGE_HID 32
#define NMAX    100000
#define EMAX    1600000
#define NBLK    296      // fused-norm grid: 2 CTAs/SM * 148 SMs
#define NTHR    512

typedef unsigned long long u64;

__device__ __forceinline__ u64 pk(float lo, float hi) {
    u64 r; asm("mov.b64 %0, {%1,%2};" : "=l"(r) : "f"(lo), "f"(hi)); return r;
}
__device__ __forceinline__ void upk(u64 v, float& lo, float& hi) {
    asm("mov.b64 {%0,%1}, %2;" : "=f"(lo), "=f"(hi) : "l"(v));
}
__device__ __forceinline__ void fma2(u64& d, u64 a, u64 b) {
    asm("fma.rn.f32x2 %0, %1, %2, %0;" : "+l"(d) : "l"(a), "l"(b));
}

// ---------------- scratch ----------------------------------------------------
static __device__ float g_ew[EMAX];
static __device__ float g_deg[NMAX];
static __device__ float g_dinv[NMAX];
static __device__ float g_xt[(long long)NMAX * OUT_C];
static __device__ float g_sum[OUT_C];
static __device__ float g_sumsq[OUT_C];
static __device__ int   g_ctr;

// ---------------- K0: deg=1, zero stats+ctr, zero out ------------------------
__global__ void k_init(float4* __restrict__ out4, int n, int nq) {
    int i = blockIdx.x * blockDim.x + threadIdx.x;
    if (i < nq) out4[i] = make_float4(0.f, 0.f, 0.f, 0.f);
    if (i < n) g_deg[i] = 1.0f;
    if (i < OUT_C) { g_sum[i] = 0.0f; g_sumsq[i] = 0.0f; }
    if (i == 0) g_ctr = 0;
}

// ---------------- K1: edge MLP, f32x2 over h-pairs, 2 edges/thread -----------
__global__ void k_edge_mlp(const float* __restrict__ ea,
                           const float* __restrict__ w1, const float* __restrict__ b1,
                           const float* __restrict__ w2, const float* __restrict__ b2,
                           const int* __restrict__ ei, int e_, int n) {
    __shared__ __align__(16) float2 swp[16 * 16];
    __shared__ __align__(8)  float2 sb1p[16];
    __shared__ float sw2[EDGE_HID];
    __shared__ float sb2;
    {
        int t = threadIdx.x;
        if (t < 256) {
            int p = t >> 4, i = t & 15;
            swp[t] = make_float2(w1[(2 * p) * EDGE_DIM + i], w1[(2 * p + 1) * EDGE_DIM + i]);
        }
        if (t < 16) sb1p[t] = make_float2(b1[2 * t], b1[2 * t + 1]);
        if (t < EDGE_HID) sw2[t] = w2[t];
        if (t == 0) sb2 = b2[0];
    }
    __syncthreads();

    int e0 = (blockIdx.x * blockDim.x + threadIdx.x) * 2;
    if (e0 >= e_) return;
    bool two = (e0 + 1) < e_;

    u64 a0p[EDGE_DIM], a1p[EDGE_DIM];
    {
        const float4* p = (const float4*)(ea + (long long)e0 * EDGE_DIM);
#pragma unroll
        for (int q = 0; q < 4; q++) {
            float4 v = p[q];
            a0p[q*4+0] = pk(v.x, v.x); a0p[q*4+1] = pk(v.y, v.y);
            a0p[q*4+2] = pk(v.z, v.z); a0p[q*4+3] = pk(v.w, v.w);
            float4 u = two ? p[q + 4] : make_float4(0.f, 0.f, 0.f, 0.f);
            a1p[q*4+0] = pk(u.x, u.x); a1p[q*4+1] = pk(u.y, u.y);
            a1p[q*4+2] = pk(u.z, u.z); a1p[q*4+3] = pk(u.w, u.w);
        }
    }

    float acc0 = sb2, acc1 = sb2;
#pragma unroll 4
    for (int p = 0; p < 16; ++p) {
        float2 sb = sb1p[p];
        u64 s0 = pk(sb.x, sb.y);
        u64 s1 = s0;
#pragma unroll
        for (int iq = 0; iq < 8; ++iq) {
            ulonglong2 w = *(const ulonglong2*)&swp[p * 16 + iq * 2];
            fma2(s0, a0p[iq*2],   w.x);
            fma2(s0, a0p[iq*2+1], w.y);
            fma2(s1, a1p[iq*2],   w.x);
            fma2(s1, a1p[iq*2+1], w.y);
        }
        float wlo = sw2[2*p], whi = sw2[2*p+1];
        float t0, t1;
        upk(s0, t0, t1);
        acc0 = fmaf(fmaxf(t0, 0.f), wlo, fmaf(fmaxf(t1, 0.f), whi, acc0));
        upk(s1, t0, t1);
        acc1 = fmaf(fmaxf(t0, 0.f), wlo, fmaf(fmaxf(t1, 0.f), whi, acc1));
    }
    float g0 = 1.0f / (1.0f + __expf(-acc0));
    g_ew[e0] = g0;
    int c0 = ei[e_ + e0];
    if ((unsigned)c0 < (unsigned)n) atomicAdd(&g_deg[c0], g0);
    if (two) {
        float g1 = 1.0f / (1.0f + __expf(-acc1));
        g_ew[e0 + 1] = g1;
        int c1 = ei[e_ + e0 + 1];
        if ((unsigned)c1 < (unsigned)n) atomicAdd(&g_deg[c1], g1);
    }
}

// ---------------- K2: dinv = rsqrt(deg) --------------------------------------
__global__ void k_dinv(int n) {
    int i = blockIdx.x * blockDim.x + threadIdx.x;
    if (i < n) g_dinv[i] = rsqrtf(g_deg[i]);
}

// ---------------- K3: xt = x @ lin_w.T (pure GEMM) ---------------------------
#define GR 128
#define KC 32
#define XROW 132
__global__ void __launch_bounds__(256, 3)
k_xt(const float* __restrict__ x, const float* __restrict__ lw, int n) {
    __shared__ __align__(16) float xs[KC][XROW];
    __shared__ __align__(16) float ws[KC][OUT_C];
    int r0 = blockIdx.x * GR;
    int tx = threadIdx.x & 15;
    int ty = threadIdx.x >> 4;
    u64 accp[4][4] = {};

    for (int k0 = 0; k0 < IN_C; k0 += KC) {
        for (int i = threadIdx.x; i < GR * (KC / 4); i += 256) {
            int r = i >> 3, kq = i & 7;
            float4 v = make_float4(0.f, 0.f, 0.f, 0.f);
            if (r0 + r < n) v = *(const float4*)(x + (long long)(r0 + r) * IN_C + k0 + kq * 4);
            xs[kq*4+0][r] = v.x; xs[kq*4+1][r] = v.y;
            xs[kq*4+2][r] = v.z; xs[kq*4+3][r] = v.w;
        }
        for (int i = threadIdx.x; i < OUT_C * (KC / 4); i += 256) {
            int o = i >> 3, kq = i & 7;
            float4 v = *(const float4*)(lw + (long long)o * IN_C + k0 + kq * 4);
            ws[kq*4+0][o] = v.x; ws[kq*4+1][o] = v.y;
            ws[kq*4+2][o] = v.z; ws[kq*4+3][o] = v.w;
        }
        __syncthreads();
#pragma unroll 8
        for (int k = 0; k < KC; ++k) {
            float4 a0 = *(const float4*)&xs[k][ty * 8];
            float4 a1 = *(const float4*)&xs[k][ty * 8 + 4];
            float4 b  = *(const float4*)&ws[k][tx * 4];
            u64 ap0 = pk(a0.x, a0.y), ap1 = pk(a0.z, a0.w);
            u64 ap2 = pk(a1.x, a1.y), ap3 = pk(a1.z, a1.w);
            u64 b0 = pk(b.x, b.x), b1 = pk(b.y, b.y), b2 = pk(b.z, b.z), b3 = pk(b.w, b.w);
            fma2(accp[0][0], ap0, b0); fma2(accp[0][1], ap0, b1);
            fma2(accp[0][2], ap0, b2); fma2(accp[0][3], ap0, b3);
            fma2(accp[1][0], ap1, b0); fma2(accp[1][1], ap1, b1);
            fma2(accp[1][2], ap1, b2); fma2(accp[1][3], ap1, b3);
            fma2(accp[2][0], ap2, b0); fma2(accp[2][1], ap2, b1);
            fma2(accp[2][2], ap2, b2); fma2(accp[2][3], ap2, b3);
            fma2(accp[3][0], ap3, b0); fma2(accp[3][1], ap3, b1);
            fma2(accp[3][2], ap3, b2); fma2(accp[3][3], ap3, b3);
        }
        __syncthreads();
    }
#pragma unroll
    for (int rp = 0; rp < 4; ++rp) {
        float lo[4], hi[4];
#pragma unroll
        for (int j = 0; j < 4; ++j) upk(accp[rp][j], lo[j], hi[j]);
        int rA = r0 + ty * 8 + rp * 2;
        int rB = rA + 1;
        if (rA < n)
            *(float4*)&g_xt[(long long)rA * OUT_C + tx * 4] = make_float4(lo[0], lo[1], lo[2], lo[3]);
        if (rB < n)
            *(float4*)&g_xt[(long long)rB * OUT_C + tx * 4] = make_float4(hi[0], hi[1], hi[2], hi[3]);
    }
}

// ---------------- K4: scatter (16 threads/edge, v4 RED) ----------------------
__global__ void k_scatter(const int* __restrict__ ei, float* __restrict__ outacc, int e_, int n) {
    long long gid = (long long)blockIdx.x * blockDim.x + threadIdx.x;
    int e = (int)(gid >> 4);
    if (e >= e_) return;
    int cg = ((int)gid & 15) * 4;
    int r = ei[e];
    int c = ei[e_ + e];
    if ((unsigned)r >= (unsigned)n || (unsigned)c >= (unsigned)n) return;
    float nrm = g_dinv[r] * g_ew[e] * g_dinv[c];
    float4 v = *(const float4*)&g_xt[(long long)r * OUT_C + cg];
    float* p = outacc + (long long)c * OUT_C + cg;
    asm volatile("red.global.add.v4.f32 [%0], {%1, %2, %3, %4};"
                 :: "l"(p), "f"(v.x * nrm), "f"(v.y * nrm), "f"(v.z * nrm), "f"(v.w * nrm)
                 : "memory");
}

// ---------------- K5: fused self-loop + bias + PReLU + GraphNorm -------------
// One kernel, device-wide arrive/spin barrier between stats and normalize.
// Grid = NBLK(296) x NTHR(512) = exactly 2 CTAs/SM on 148 SMs (co-resident).
__global__ void __launch_bounds__(NTHR, 2)
k_fused_norm(float* __restrict__ y, const float* __restrict__ bias,
             const float* __restrict__ pa,
             const float* __restrict__ gw, const float* __restrict__ gb,
             const float* __restrict__ gms, int n, int rowsPerBlk) {
    extern __shared__ float sm[];                 // rowsPerBlk * 64
    __shared__ float ss[NTHR], sq[NTHR];

    int tid = threadIdx.x;
    int c = tid & 63;
    int rl = tid >> 6;                            // 8 row lanes
    int r0 = blockIdx.x * rowsPerBlk;
    int r1 = min(n, r0 + rowsPerBlk);

    float b = bias[c];
    float a = pa[0];
    float s = 0.0f, q = 0.0f;

    for (int r = r0 + rl; r < r1; r += NTHR / 64) {
        long long idx = (long long)r * OUT_C + c;
        float d = g_dinv[r];
        float v = fmaf(d * d, g_xt[idx], y[idx]) + b;   // scatter-sum + self-loop + bias
        v = (v >= 0.0f) ? v : a * v;
        sm[(r - r0) * OUT_C + c] = v;
        s += v;
        q = fmaf(v, v, q);
    }
    ss[tid] = s; sq[tid] = q;
    __syncthreads();
    if (tid < 64) {
        s = 0.f; q = 0.f;
#pragma unroll
        for (int i = 0; i < NTHR; i += 64) { s += ss[tid + i]; q += sq[tid + i]; }
        atomicAdd(&g_sum[tid], s);
        atomicAdd(&g_sumsq[tid], q);
    }
    __syncthreads();

    // device-wide barrier
    if (tid == 0) {
        __threadfence();
        atomicAdd(&g_ctr, 1);
        while (*((volatile int*)&g_ctr) < gridDim.x) __nanosleep(40);
    }
    __syncthreads();
    __threadfence();

    float invn = 1.0f / (float)n;
    float m  = (*((volatile float*)&g_sum[c]))   * invn;
    float qq = (*((volatile float*)&g_sumsq[c])) * invn;
    float sc = gms[c];
    float var = fmaf(-2.0f * sc * m, m, qq) + sc * sc * m * m;
    float w = gw[c] * rsqrtf(var + 1e-5f);
    float smean = sc * m;
    float bb = gb[c];

    for (int r = r0 + rl; r < r1; r += NTHR / 64) {
        long long idx = (long long)r * OUT_C + c;
        y[idx] = fmaf(sm[(r - r0) * OUT_C + c] - smean, w, bb);
    }
}

// ---------------- launch -------------------------------------------------------
extern "C" void kernel_launch(void* const* d_in, const int* in_sizes, int n_in,
                              void* d_out, int out_size) {
    const float* x    = (const float*)d_in[0];
    const int*   ei   = (const int*)d_in[1];
    const float* ea   = (const float*)d_in[2];
    const float* lw   = (const float*)d_in[3];
    const float* bias = (const float*)d_in[4];
    const float* w1   = (const float*)d_in[5];
    const float* b1   = (const float*)d_in[6];
    const float* w2   = (const float*)d_in[7];
    const float* b2   = (const float*)d_in[8];
    const float* pa   = (const float*)d_in[9];
    const float* gw   = (const float*)d_in[10];
    const float* gb   = (const float*)d_in[11];
    const float* gms  = (const float*)d_in[12];
    float* out = (float*)d_out;

    int n = in_sizes[0] / IN_C;
    int e = in_sizes[1] / 2;
    int rowsPerBlk = (n + NBLK - 1) / NBLK;
    size_t smBytes = (size_t)rowsPerBlk * OUT_C * sizeof(float);

    static cudaStream_t s1 = nullptr;
    static cudaEvent_t evFork = nullptr, evJoin = nullptr;
    if (s1 == nullptr) {
        cudaStreamCreateWithFlags(&s1, cudaStreamNonBlocking);
        cudaEventCreateWithFlags(&evFork, cudaEventDisableTiming);
        cudaEventCreateWithFlags(&evJoin, cudaEventDisableTiming);
        cudaFuncSetAttribute(k_fused_norm, cudaFuncAttributeMaxDynamicSharedMemorySize, 110 * 1024);
    }

    // fork: GEMM on side stream, topology pipeline on main stream
    cudaEventRecord(evFork, 0);
    cudaStreamWaitEvent(s1, evFork, 0);
    k_xt<<<(n + GR - 1) / GR, 256, 0, s1>>>(x, lw, n);
    cudaEventRecord(evJoin, s1);

    int nq = n * (OUT_C / 4);
    k_init<<<(nq + 255) / 256, 256>>>((float4*)out, n, nq);
    int th_mlp = (e + 1) / 2;
    k_edge_mlp<<<(th_mlp + 255) / 256, 256>>>(ea, w1, b1, w2, b2, ei, e, n);
    k_dinv<<<(n + 255) / 256, 256>>>(n);

    cudaStreamWaitEvent(0, evJoin, 0);

    long long tot = (long long)e * 16;
    k_scatter<<<(unsigned)((tot + 255) / 256), 256>>>(ei, out, e, n);
    k_fused_norm<<<NBLK, NTHR, smBytes>>>(out, bias, pa, gw, gb, gms, n, rowsPerBlk);
}

// round 8
// speedup vs baseline: 1.9067x; 1.0910x over previous
#include <cuda_runtime.h>

#define IN_C    128
#define OUT_C   64
#define EDGE_DIM 16
#define EDGE_HID 32
#define NMAX    100000
#define EMAX    1600000
#define NBLK    296
#define NTHR    512
#define SCANB   1024

typedef unsigned long long u64;

__device__ __forceinline__ u64 pk(float lo, float hi) {
    u64 r; asm("mov.b64 %0, {%1,%2};" : "=l"(r) : "f"(lo), "f"(hi)); return r;
}
__device__ __forceinline__ void upk(u64 v, float& lo, float& hi) {
    asm("mov.b64 {%0,%1}, %2;" : "=f"(lo), "=f"(hi) : "l"(v));
}
__device__ __forceinline__ void fma2(u64& d, u64 a, u64 b) {
    asm("fma.rn.f32x2 %0, %1, %2, %0;" : "+l"(d) : "l"(a), "l"(b));
}

// ---------------- scratch ----------------------------------------------------
static __device__ float g_ew[EMAX];
static __device__ float g_deg[NMAX];
static __device__ float g_dinv[NMAX];
static __device__ float g_xt[(long long)NMAX * OUT_C];
static __device__ float g_sum[OUT_C];
static __device__ float g_sumsq[OUT_C];
static __device__ int   g_ctr;
// CSR
static __device__ int   g_cnt[NMAX];
static __device__ int   g_base[NMAX];
static __device__ int   g_cur[NMAX];
static __device__ int   g_bsum[(NMAX + SCANB - 1) / SCANB];
static __device__ int   g_boff[(NMAX + SCANB - 1) / SCANB];
static __device__ int   g_src[EMAX];
static __device__ int   g_eid[EMAX];

// ---------------- K0: deg=1, zero stats+ctr ----------------------------------
__global__ void k_init(int n) {
    int i = blockIdx.x * blockDim.x + threadIdx.x;
    if (i < n) g_deg[i] = 1.0f;
    if (i < OUT_C) { g_sum[i] = 0.0f; g_sumsq[i] = 0.0f; }
    if (i == 0) g_ctr = 0;
}

// ---------------- CSR build (stream2, depends only on edge_index) ------------
__global__ void k_zero_cnt(int n) {
    int i = blockIdx.x * blockDim.x + threadIdx.x;
    if (i < n) g_cnt[i] = 0;
}
__global__ void k_hist(const int* __restrict__ ei, int e_, int n) {
    int i = blockIdx.x * blockDim.x + threadIdx.x;
    if (i >= e_) return;
    int c = ei[e_ + i];
    if ((unsigned)c < (unsigned)n) atomicAdd(&g_cnt[c], 1);
}
__global__ void k_scan1(int n) {
    __shared__ int s[SCANB];
    int t = threadIdx.x;
    int i = blockIdx.x * SCANB + t;
    int v = (i < n) ? g_cnt[i] : 0;
    s[t] = v;
    __syncthreads();
#pragma unroll
    for (int off = 1; off < SCANB; off <<= 1) {
        int x = (t >= off) ? s[t - off] : 0;
        __syncthreads();
        s[t] += x;
        __syncthreads();
    }
    if (i < n) g_base[i] = s[t] - v;              // exclusive within block
    if (t == SCANB - 1) g_bsum[blockIdx.x] = s[t];
}
__global__ void k_scan2(int nb) {
    __shared__ int s[128];
    int t = threadIdx.x;
    int v = (t < nb) ? g_bsum[t] : 0;
    s[t] = v;
    __syncthreads();
#pragma unroll
    for (int off = 1; off < 128; off <<= 1) {
        int x = (t >= off) ? s[t - off] : 0;
        __syncthreads();
        s[t] += x;
        __syncthreads();
    }
    if (t < nb) g_boff[t] = s[t] - v;             // exclusive
}
__global__ void k_scan3(int n) {
    int i = blockIdx.x * blockDim.x + threadIdx.x;
    if (i >= n) return;
    int b = g_base[i] + g_boff[i / SCANB];
    g_base[i] = b;
    g_cur[i] = b;
}
__global__ void k_fill(const int* __restrict__ ei, int e_, int n) {
    int i = blockIdx.x * blockDim.x + threadIdx.x;
    if (i >= e_) return;
    int r = ei[i];
    int c = ei[e_ + i];
    if ((unsigned)r >= (unsigned)n || (unsigned)c >= (unsigned)n) return;
    int slot = atomicAdd(&g_cur[c], 1);
    g_src[slot] = r;
    g_eid[slot] = i;
}

// ---------------- K1: edge MLP, f32x2 over h-pairs, 2 edges/thread -----------
__global__ void k_edge_mlp(const float* __restrict__ ea,
                           const float* __restrict__ w1, const float* __restrict__ b1,
                           const float* __restrict__ w2, const float* __restrict__ b2,
                           const int* __restrict__ ei, int e_, int n) {
    __shared__ __align__(16) float2 swp[16 * 16];
    __shared__ __align__(8)  float2 sb1p[16];
    __shared__ float sw2[EDGE_HID];
    __shared__ float sb2;
    {
        int t = threadIdx.x;
        if (t < 256) {
            int p = t >> 4, i = t & 15;
            swp[t] = make_float2(w1[(2 * p) * EDGE_DIM + i], w1[(2 * p + 1) * EDGE_DIM + i]);
        }
        if (t < 16) sb1p[t] = make_float2(b1[2 * t], b1[2 * t + 1]);
        if (t < EDGE_HID) sw2[t] = w2[t];
        if (t == 0) sb2 = b2[0];
    }
    __syncthreads();

    int e0 = (blockIdx.x * blockDim.x + threadIdx.x) * 2;
    if (e0 >= e_) return;
    bool two = (e0 + 1) < e_;

    u64 a0p[EDGE_DIM], a1p[EDGE_DIM];
    {
        const float4* p = (const float4*)(ea + (long long)e0 * EDGE_DIM);
#pragma unroll
        for (int q = 0; q < 4; q++) {
            float4 v = p[q];
            a0p[q*4+0] = pk(v.x, v.x); a0p[q*4+1] = pk(v.y, v.y);
            a0p[q*4+2] = pk(v.z, v.z); a0p[q*4+3] = pk(v.w, v.w);
            float4 u = two ? p[q + 4] : make_float4(0.f, 0.f, 0.f, 0.f);
            a1p[q*4+0] = pk(u.x, u.x); a1p[q*4+1] = pk(u.y, u.y);
            a1p[q*4+2] = pk(u.z, u.z); a1p[q*4+3] = pk(u.w, u.w);
        }
    }

    float acc0 = sb2, acc1 = sb2;
#pragma unroll 4
    for (int p = 0; p < 16; ++p) {
        float2 sb = sb1p[p];
        u64 s0 = pk(sb.x, sb.y);
        u64 s1 = s0;
#pragma unroll
        for (int iq = 0; iq < 8; ++iq) {
            ulonglong2 w = *(const ulonglong2*)&swp[p * 16 + iq * 2];
            fma2(s0, a0p[iq*2],   w.x);
            fma2(s0, a0p[iq*2+1], w.y);
            fma2(s1, a1p[iq*2],   w.x);
            fma2(s1, a1p[iq*2+1], w.y);
        }
        float wlo = sw2[2*p], whi = sw2[2*p+1];
        float t0, t1;
        upk(s0, t0, t1);
        acc0 = fmaf(fmaxf(t0, 0.f), wlo, fmaf(fmaxf(t1, 0.f), whi, acc0));
        upk(s1, t0, t1);
        acc1 = fmaf(fmaxf(t0, 0.f), wlo, fmaf(fmaxf(t1, 0.f), whi, acc1));
    }
    float g0 = 1.0f / (1.0f + __expf(-acc0));
    g_ew[e0] = g0;
    int c0 = ei[e_ + e0];
    if ((unsigned)c0 < (unsigned)n) atomicAdd(&g_deg[c0], g0);
    if (two) {
        float g1 = 1.0f / (1.0f + __expf(-acc1));
        g_ew[e0 + 1] = g1;
        int c1 = ei[e_ + e0 + 1];
        if ((unsigned)c1 < (unsigned)n) atomicAdd(&g_deg[c1], g1);
    }
}

// ---------------- K2: dinv = rsqrt(deg) --------------------------------------
__global__ void k_dinv(int n) {
    int i = blockIdx.x * blockDim.x + threadIdx.x;
    if (i < n) g_dinv[i] = rsqrtf(g_deg[i]);
}

// ---------------- K3: xt = x @ lin_w.T (pure GEMM) ---------------------------
#define GR 128
#define KC 32
#define XROW 132
__global__ void __launch_bounds__(256, 3)
k_xt(const float* __restrict__ x, const float* __restrict__ lw, int n) {
    __shared__ __align__(16) float xs[KC][XROW];
    __shared__ __align__(16) float ws[KC][OUT_C];
    int r0 = blockIdx.x * GR;
    int tx = threadIdx.x & 15;
    int ty = threadIdx.x >> 4;
    u64 accp[4][4] = {};

    for (int k0 = 0; k0 < IN_C; k0 += KC) {
        for (int i = threadIdx.x; i < GR * (KC / 4); i += 256) {
            int r = i >> 3, kq = i & 7;
            float4 v = make_float4(0.f, 0.f, 0.f, 0.f);
            if (r0 + r < n) v = *(const float4*)(x + (long long)(r0 + r) * IN_C + k0 + kq * 4);
            xs[kq*4+0][r] = v.x; xs[kq*4+1][r] = v.y;
            xs[kq*4+2][r] = v.z; xs[kq*4+3][r] = v.w;
        }
        for (int i = threadIdx.x; i < OUT_C * (KC / 4); i += 256) {
            int o = i >> 3, kq = i & 7;
            float4 v = *(const float4*)(lw + (long long)o * IN_C + k0 + kq * 4);
            ws[kq*4+0][o] = v.x; ws[kq*4+1][o] = v.y;
            ws[kq*4+2][o] = v.z; ws[kq*4+3][o] = v.w;
        }
        __syncthreads();
#pragma unroll 8
        for (int k = 0; k < KC; ++k) {
            float4 a0 = *(const float4*)&xs[k][ty * 8];
            float4 a1 = *(const float4*)&xs[k][ty * 8 + 4];
            float4 b  = *(const float4*)&ws[k][tx * 4];
            u64 ap0 = pk(a0.x, a0.y), ap1 = pk(a0.z, a0.w);
            u64 ap2 = pk(a1.x, a1.y), ap3 = pk(a1.z, a1.w);
            u64 b0 = pk(b.x, b.x), b1 = pk(b.y, b.y), b2 = pk(b.z, b.z), b3 = pk(b.w, b.w);
            fma2(accp[0][0], ap0, b0); fma2(accp[0][1], ap0, b1);
            fma2(accp[0][2], ap0, b2); fma2(accp[0][3], ap0, b3);
            fma2(accp[1][0], ap1, b0); fma2(accp[1][1], ap1, b1);
            fma2(accp[1][2], ap1, b2); fma2(accp[1][3], ap1, b3);
            fma2(accp[2][0], ap2, b0); fma2(accp[2][1], ap2, b1);
            fma2(accp[2][2], ap2, b2); fma2(accp[2][3], ap2, b3);
            fma2(accp[3][0], ap3, b0); fma2(accp[3][1], ap3, b1);
            fma2(accp[3][2], ap3, b2); fma2(accp[3][3], ap3, b3);
        }
        __syncthreads();
    }
#pragma unroll
    for (int rp = 0; rp < 4; ++rp) {
        float lo[4], hi[4];
#pragma unroll
        for (int j = 0; j < 4; ++j) upk(accp[rp][j], lo[j], hi[j]);
        int rA = r0 + ty * 8 + rp * 2;
        int rB = rA + 1;
        if (rA < n)
            *(float4*)&g_xt[(long long)rA * OUT_C + tx * 4] = make_float4(lo[0], lo[1], lo[2], lo[3]);
        if (rB < n)
            *(float4*)&g_xt[(long long)rB * OUT_C + tx * 4] = make_float4(hi[0], hi[1], hi[2], hi[3]);
    }
}

// ---------------- K4: gather (1 warp per target node, no atomics) ------------
__global__ void __launch_bounds__(256)
k_gather(float* __restrict__ out, int n) {
    int node = blockIdx.x * 8 + (threadIdx.x >> 5);
    if (node >= n) return;
    int lane = threadIdx.x & 31;
    int beg = g_base[node];
    int cnt = g_cnt[node];
    float2 acc = make_float2(0.f, 0.f);

    for (int j0 = 0; j0 < cnt; j0 += 32) {
        int m = min(32, cnt - j0);
        int src = 0; float a = 0.f;
        if (lane < m) {
            int slot = beg + j0 + lane;
            src = g_src[slot];
            a = g_dinv[src] * g_ew[g_eid[slot]];
        }
        for (int j = 0; j < m; ++j) {
            int   s  = __shfl_sync(0xffffffffu, src, j);
            float aj = __shfl_sync(0xffffffffu, a, j);
            float2 v = *(const float2*)&g_xt[(long long)s * OUT_C + lane * 2];
            acc.x = fmaf(aj, v.x, acc.x);
            acc.y = fmaf(aj, v.y, acc.y);
        }
    }
    float dc = g_dinv[node];
    acc.x *= dc; acc.y *= dc;
    *(float2*)&out[(long long)node * OUT_C + lane * 2] = acc;
}

// ---------------- K5: fused self-loop + bias + PReLU + GraphNorm -------------
__global__ void __launch_bounds__(NTHR, 2)
k_fused_norm(float* __restrict__ y, const float* __restrict__ bias,
             const float* __restrict__ pa,
             const float* __restrict__ gw, const float* __restrict__ gb,
             const float* __restrict__ gms, int n, int rowsPerBlk) {
    extern __shared__ float sm[];
    __shared__ float ss[NTHR], sq[NTHR];

    int tid = threadIdx.x;
    int c = tid & 63;
    int rl = tid >> 6;
    int r0 = blockIdx.x * rowsPerBlk;
    int r1 = min(n, r0 + rowsPerBlk);

    float b = bias[c];
    float a = pa[0];
    float s = 0.0f, q = 0.0f;

    for (int r = r0 + rl; r < r1; r += NTHR / 64) {
        long long idx = (long long)r * OUT_C + c;
        float d = g_dinv[r];
        float v = fmaf(d * d, g_xt[idx], y[idx]) + b;
        v = (v >= 0.0f) ? v : a * v;
        sm[(r - r0) * OUT_C + c] = v;
        s += v;
        q = fmaf(v, v, q);
    }
    ss[tid] = s; sq[tid] = q;
    __syncthreads();
    if (tid < 64) {
        s = 0.f; q = 0.f;
#pragma unroll
        for (int i = 0; i < NTHR; i += 64) { s += ss[tid + i]; q += sq[tid + i]; }
        atomicAdd(&g_sum[tid], s);
        atomicAdd(&g_sumsq[tid], q);
    }
    __syncthreads();

    if (tid == 0) {
        __threadfence();
        atomicAdd(&g_ctr, 1);
        while (*((volatile int*)&g_ctr) < gridDim.x) __nanosleep(40);
    }
    __syncthreads();
    __threadfence();

    float invn = 1.0f / (float)n;
    float m  = (*((volatile float*)&g_sum[c]))   * invn;
    float qq = (*((volatile float*)&g_sumsq[c])) * invn;
    float sc = gms[c];
    float var = fmaf(-2.0f * sc * m, m, qq) + sc * sc * m * m;
    float w = gw[c] * rsqrtf(var + 1e-5f);
    float smean = sc * m;
    float bb = gb[c];

    for (int r = r0 + rl; r < r1; r += NTHR / 64) {
        long long idx = (long long)r * OUT_C + c;
        y[idx] = fmaf(sm[(r - r0) * OUT_C + c] - smean, w, bb);
    }
}

// ---------------- launch -------------------------------------------------------
extern "C" void kernel_launch(void* const* d_in, const int* in_sizes, int n_in,
                              void* d_out, int out_size) {
    const float* x    = (const float*)d_in[0];
    const int*   ei   = (const int*)d_in[1];
    const float* ea   = (const float*)d_in[2];
    const float* lw   = (const float*)d_in[3];
    const float* bias = (const float*)d_in[4];
    const float* w1   = (const float*)d_in[5];
    const float* b1   = (const float*)d_in[6];
    const float* w2   = (const float*)d_in[7];
    const float* b2   = (const float*)d_in[8];
    const float* pa   = (const float*)d_in[9];
    const float* gw   = (const float*)d_in[10];
    const float* gb   = (const float*)d_in[11];
    const float* gms  = (const float*)d_in[12];
    float* out = (float*)d_out;

    int n = in_sizes[0] / IN_C;
    int e = in_sizes[1] / 2;
    int rowsPerBlk = (n + NBLK - 1) / NBLK;
    size_t smBytes = (size_t)rowsPerBlk * OUT_C * sizeof(float);
    int nb = (n + SCANB - 1) / SCANB;

    static cudaStream_t s1 = nullptr, s2 = nullptr;
    static cudaEvent_t evFork = nullptr, evJ1 = nullptr, evJ2 = nullptr;
    if (s1 == nullptr) {
        cudaStreamCreateWithFlags(&s1, cudaStreamNonBlocking);
        cudaStreamCreateWithFlags(&s2, cudaStreamNonBlocking);
        cudaEventCreateWithFlags(&evFork, cudaEventDisableTiming);
        cudaEventCreateWithFlags(&evJ1, cudaEventDisableTiming);
        cudaEventCreateWithFlags(&evJ2, cudaEventDisableTiming);
        cudaFuncSetAttribute(k_fused_norm, cudaFuncAttributeMaxDynamicSharedMemorySize, 110 * 1024);
    }

    cudaEventRecord(evFork, 0);
    cudaStreamWaitEvent(s1, evFork, 0);
    cudaStreamWaitEvent(s2, evFork, 0);

    // stream1: GEMM
    k_xt<<<(n + GR - 1) / GR, 256, 0, s1>>>(x, lw, n);
    cudaEventRecord(evJ1, s1);

    // stream2: CSR build (depends only on edge_index)
    k_zero_cnt<<<(n + 255) / 256, 256, 0, s2>>>(n);
    k_hist<<<(e + 255) / 256, 256, 0, s2>>>(ei, e, n);
    k_scan1<<<nb, SCANB, 0, s2>>>(n);
    k_scan2<<<1, 128, 0, s2>>>(nb);
    k_scan3<<<(n + 255) / 256, 256, 0, s2>>>(n);
    k_fill<<<(e + 255) / 256, 256, 0, s2>>>(ei, e, n);
    cudaEventRecord(evJ2, s2);

    // main stream: gate pipeline
    k_init<<<(n + 255) / 256, 256>>>(n);
    int th_mlp = (e + 1) / 2;
    k_edge_mlp<<<(th_mlp + 255) / 256, 256>>>(ea, w1, b1, w2, b2, ei, e, n);
    k_dinv<<<(n + 255) / 256, 256>>>(n);

    cudaStreamWaitEvent(0, evJ1, 0);
    cudaStreamWaitEvent(0, evJ2, 0);

    k_gather<<<(n + 7) / 8, 256>>>(out, n);
    k_fused_norm<<<NBLK, NTHR, smBytes>>>(out, bias, pa, gw, gb, gms, n, rowsPerBlk);
}